// round 3
// baseline (speedup 1.0000x reference)
#include <cuda_runtime.h>
#include <math.h>

// DCN collapsed-affine, round 3: single fused persistent kernel.
// Chain (blocks 0..31, sub-barriers):  v3 -> v2 -> u -> q,r
// All blocks: gather pass1 (cw0,cw1,cw2,pw_x dots) overlapped with chain,
// global barrier, then pass2 (q dot from L2-hot rows) + epilogue.

#define EPSF 1e-5f

constexpr int Bn   = 4096;
constexpr int Fn   = 26;
constexpr int Vn   = 10000;
constexpr int Dn   = 64;
constexpr int D0   = 1664;   // Fn*Dn
constexpr int NUMB = 13;
constexpr int INW  = 1677;   // D0 + NUMB
constexpr int H1   = 1024;
constexpr int H2   = 512;
constexpr int H3   = 256;

constexpr int GRID   = 128;
constexpr int NTHR   = 1024;
constexpr int CHAINB = 32;

// Scratch (device globals: no allocation allowed)
__device__ float g_v3p[8][H2];
__device__ float g_v2p[16][H1];
__device__ float g_up[32][1792];
__device__ float g_q[1792];
__device__ float g_rp[2];
__device__ unsigned long long g_bar_chain;  // zero-init; stays multiple of 32
__device__ unsigned long long g_bar_all;    // zero-init; stays multiple of 128

__device__ __forceinline__ float warp_sum(float v) {
    #pragma unroll
    for (int o = 16; o; o >>= 1) v += __shfl_xor_sync(0xffffffffu, v, o);
    return v;
}

// Grid-subset barrier. Monotonic counter: each use adds exactly n, so the
// counter remains a multiple of n across uses AND across graph replays.
__device__ __forceinline__ void barrier_sync(unsigned long long* ctr, unsigned n) {
    __threadfence();          // release: all this thread's stores visible (also flushes L1)
    __syncthreads();
    if (threadIdx.x == 0) {
        unsigned long long t = atomicAdd(ctr, 1ULL);
        unsigned long long target = (t / n + 1ULL) * (unsigned long long)n;
        while (*((volatile unsigned long long*)ctr) < target) __nanosleep(32);
    }
    __syncthreads();
    __threadfence();          // acquire: subsequent loads see remote stores
}

__global__ __launch_bounds__(NTHR, 1) void k_fused(
    const float* __restrict__ numb, const int* __restrict__ cat,
    const float* __restrict__ emb,
    const float* __restrict__ bn0,
    const float* __restrict__ w1, const float* __restrict__ b1, const float* __restrict__ bn1,
    const float* __restrict__ w2, const float* __restrict__ b2, const float* __restrict__ bn2,
    const float* __restrict__ w3, const float* __restrict__ b3, const float* __restrict__ bn3,
    const float* __restrict__ cross_w, const float* __restrict__ cross_b,
    const float* __restrict__ pred_w, const float* __restrict__ pred_b,
    float* __restrict__ out) {

    __shared__ float2 sv0[832], sv1[832], sv2[832], sv3[832], sv4[832];
    __shared__ float  ts[32];        // chain: a.*(vec) staging
    __shared__ float  sred[512];     // chain: v3 half-reduce
    __shared__ float  red[3][32];
    __shared__ float  s_sc[4];       // Sc1, Sc2, Sp, r
    __shared__ float  s_qn[16];

    const int tid  = threadIdx.x;
    const int bid  = blockIdx.x;
    const int warp = tid >> 5;
    const int lane = tid & 31;
    const int row  = bid * 32 + warp;

    // per-lane category index for this warp's row (persists across phases)
    int myidx = (lane < Fn) ? cat[row * Fn + lane] : 0;

    // ================= chain (blocks 0..31) =================
    if (bid < CHAINB) {
        // ---- v3 partials: blocks 0..7, i-chunk of 32 rows each ----
        if (bid < 8) {
            int i0 = bid * 32;
            if (tid < 32) {
                int i = i0 + tid;
                float a3 = bn3[i] * rsqrtf(bn3[3 * H3 + i] + EPSF);
                ts[tid] = a3 * pred_w[D0 + i];
            }
            __syncthreads();
            int j = tid & 511, h = tid >> 9;
            float acc = 0.f;
            #pragma unroll
            for (int i = 0; i < 16; i++)
                acc += w3[(i0 + h * 16 + i) * H2 + j] * ts[h * 16 + i];
            if (h == 1) sred[j] = acc;
            __syncthreads();
            if (h == 0) g_v3p[bid][j] = acc + sred[j];
        }
        barrier_sync(&g_bar_chain, CHAINB);

        // ---- v2 partials: blocks 0..15, i-chunk 32, j = tid (1024) ----
        if (bid < 16) {
            int i0 = bid * 32;
            if (tid < 32) {
                int i = i0 + tid;
                float v3 = 0.f;
                #pragma unroll
                for (int p = 0; p < 8; p++) v3 += g_v3p[p][i];
                float a2 = bn2[i] * rsqrtf(bn2[3 * H2 + i] + EPSF);
                ts[tid] = a2 * v3;
            }
            __syncthreads();
            float acc = 0.f;
            #pragma unroll 8
            for (int i = 0; i < 32; i++)
                acc += w2[(i0 + i) * H1 + tid] * ts[i];
            g_v2p[bid][tid] = acc;
        }
        barrier_sync(&g_bar_chain, CHAINB);

        // ---- u partials: all 32 chain blocks, i-chunk 32 ----
        {
            int i0 = bid * 32;
            if (tid < 32) {
                int i = i0 + tid;
                float v2 = 0.f;
                #pragma unroll
                for (int p = 0; p < 16; p++) v2 += g_v2p[p][i];
                float a1 = bn1[i] * rsqrtf(bn1[3 * H1 + i] + EPSF);
                ts[tid] = a1 * v2;
            }
            __syncthreads();
            float acc = 0.f;
            #pragma unroll 8
            for (int i = 0; i < 32; i++)
                acc += w1[(size_t)(i0 + i) * INW + tid] * ts[i];
            g_up[bid][tid] = acc;
            if (tid < INW - 1024) {
                int j2 = 1024 + tid;
                float acc2 = 0.f;
                #pragma unroll 8
                for (int i = 0; i < 32; i++)
                    acc2 += w1[(size_t)(i0 + i) * INW + j2] * ts[i];
                g_up[bid][j2] = acc2;
            }
        }
        barrier_sync(&g_bar_chain, CHAINB);

        // ---- scalars: blocks 0..1 compute q and r-halves ----
        if (bid < 2) {
            float r = 0.f;
            if (bid == 0) {
                int j = tid;
                float u = 0.f;
                #pragma unroll
                for (int p = 0; p < 32; p++) u += g_up[p][j];
                float a0 = bn0[j] * rsqrtf(bn0[3 * INW + j] + EPSF);
                float c0 = bn0[INW + j] - bn0[2 * INW + j] * a0;
                g_q[j] = a0 * u;
                r = c0 * u;
                float v2 = 0.f;
                #pragma unroll
                for (int p = 0; p < 16; p++) v2 += g_v2p[p][j];
                float a1 = bn1[j] * rsqrtf(bn1[3 * H1 + j] + EPSF);
                r += (a1 * b1[j] + bn1[H1 + j] - bn1[2 * H1 + j] * a1) * v2;
            } else {
                int j = 1024 + tid;
                if (j < INW) {
                    float u = 0.f;
                    #pragma unroll
                    for (int p = 0; p < 32; p++) u += g_up[p][j];
                    float a0 = bn0[j] * rsqrtf(bn0[3 * INW + j] + EPSF);
                    float c0 = bn0[INW + j] - bn0[2 * INW + j] * a0;
                    g_q[j] = a0 * u;
                    r = c0 * u;
                }
                if (tid < H2) {
                    float v3 = 0.f;
                    #pragma unroll
                    for (int p = 0; p < 8; p++) v3 += g_v3p[p][tid];
                    float a2 = bn2[tid] * rsqrtf(bn2[3 * H2 + tid] + EPSF);
                    r += (a2 * b2[tid] + bn2[H2 + tid] - bn2[2 * H2 + tid] * a2) * v3;
                }
                if (tid < H3) {
                    float a3 = bn3[tid] * rsqrtf(bn3[3 * H3 + tid] + EPSF);
                    r += (a3 * b3[tid] + bn3[H3 + tid] - bn3[2 * H3 + tid] * a3) * pred_w[D0 + tid];
                }
                if (tid == 0) r += pred_b[0];
            }
            r = warp_sum(r);
            if (lane == 0) red[0][warp] = r;
            __syncthreads();
            if (tid < 32) {
                float rb = warp_sum(red[0][tid]);
                if (tid == 0) g_rp[bid] = rb;
            }
        }
    }

    // ============ staging + Sc sums (all blocks) ============
    {
        float p1 = 0.f, p2 = 0.f, p3 = 0.f;
        const float2* cwp = (const float2*)cross_w;
        const float2* pwp = (const float2*)pred_w;
        if (tid < 832) {
            float2 c0 = cwp[tid];
            float2 c1 = cwp[832 + tid];
            float2 c2 = cwp[1664 + tid];
            float2 pw = pwp[tid];
            sv0[tid] = c0; sv1[tid] = c1; sv2[tid] = c2; sv3[tid] = pw;
            p1 = c1.x + c1.y; p2 = c2.x + c2.y; p3 = pw.x + pw.y;
        }
        p1 = warp_sum(p1); p2 = warp_sum(p2); p3 = warp_sum(p3);
        if (lane == 0) { red[0][warp] = p1; red[1][warp] = p2; red[2][warp] = p3; }
        __syncthreads();
        if (tid < 32) {
            float a = warp_sum(red[0][tid]);
            float b = warp_sum(red[1][tid]);
            float c = warp_sum(red[2][tid]);
            if (tid == 0) { s_sc[0] = a; s_sc[1] = b; s_sc[2] = c; }
        }
        __syncthreads();
    }

    // ============ gather pass 1: chain-independent dots (DRAM) ============
    float acc0 = 0.f, acc1 = 0.f, acc2 = 0.f, acc3 = 0.f;
    #pragma unroll
    for (int f = 0; f < Fn; f++) {
        int idx = __shfl_sync(0xffffffffu, myidx, f);
        const float2* src = reinterpret_cast<const float2*>(
            emb + (size_t)f * (Vn * Dn) + (size_t)idx * Dn);
        float2 e = src[lane];
        int b = f * 32 + lane;
        float2 c;
        c = sv0[b]; acc0 += e.x * c.x + e.y * c.y;
        c = sv1[b]; acc1 += e.x * c.x + e.y * c.y;
        c = sv2[b]; acc2 += e.x * c.x + e.y * c.y;
        c = sv3[b]; acc3 += e.x * c.x + e.y * c.y;
    }

    // ============ global barrier: q, r ready ============
    barrier_sync(&g_bar_all, GRID);

    {
        const float2* qp = (const float2*)g_q;
        if (tid < 832) sv4[tid] = qp[tid];
        if (tid < NUMB) s_qn[tid] = g_q[D0 + tid];
        if (tid == 0) s_sc[3] = g_rp[0] + g_rp[1];
    }
    __syncthreads();

    // ============ gather pass 2: q dot (rows hot in L2) ============
    float acc4 = 0.f;
    #pragma unroll
    for (int f = 0; f < Fn; f++) {
        int idx = __shfl_sync(0xffffffffu, myidx, f);
        const float2* src = reinterpret_cast<const float2*>(
            emb + (size_t)f * (Vn * Dn) + (size_t)idx * Dn);
        float2 e = src[lane];
        float2 c = sv4[f * 32 + lane];
        acc4 += e.x * c.x + e.y * c.y;
    }
    if (lane < NUMB) acc4 += numb[row * NUMB + lane] * s_qn[lane];

    acc0 = warp_sum(acc0);
    acc1 = warp_sum(acc1);
    acc2 = warp_sum(acc2);
    acc3 = warp_sum(acc3);
    acc4 = warp_sum(acc4);

    if (lane == 0) {
        float cb0 = cross_b[0], cb1 = cross_b[1], cb2 = cross_b[2];
        float Sc1 = s_sc[0], Sc2 = s_sc[1], Sp = s_sc[2], rtot = s_sc[3];

        float al = acc0 + 1.f;          // x1 = (s0+1) x0 + cb0
        float be = cb0;
        float sd1 = al * acc1 + be * Sc1;
        al = (sd1 + 1.f) * al;
        be = (sd1 + 1.f) * be + cb1;
        float sd2 = al * acc2 + be * Sc2;
        al = (sd2 + 1.f) * al;
        be = (sd2 + 1.f) * be + cb2;

        float z = al * acc3 + be * Sp + acc4 + rtot;
        out[row] = 1.f / (1.f + expf(-z));
    }
}

// ---------------------------------------------------------------------------
extern "C" void kernel_launch(void* const* d_in, const int* in_sizes, int n_in,
                              void* d_out, int out_size) {
    const float* numb    = (const float*)d_in[0];
    const int*   cat     = (const int*)  d_in[1];
    const float* emb     = (const float*)d_in[2];
    const float* bn0     = (const float*)d_in[3];
    const float* w1      = (const float*)d_in[4];
    const float* b1      = (const float*)d_in[5];
    const float* bn1     = (const float*)d_in[6];
    const float* w2      = (const float*)d_in[7];
    const float* b2      = (const float*)d_in[8];
    const float* bn2     = (const float*)d_in[9];
    const float* w3      = (const float*)d_in[10];
    const float* b3      = (const float*)d_in[11];
    const float* bn3     = (const float*)d_in[12];
    const float* cross_w = (const float*)d_in[13];
    const float* cross_b = (const float*)d_in[14];
    const float* pred_w  = (const float*)d_in[15];
    const float* pred_b  = (const float*)d_in[16];
    float* out = (float*)d_out;

    k_fused<<<GRID, NTHR>>>(numb, cat, emb, bn0, w1, b1, bn1, w2, b2, bn2,
                            w3, b3, bn3, cross_w, cross_b, pred_w, pred_b, out);
}